// round 14
// baseline (speedup 1.0000x reference)
#include <cuda_runtime.h>
#include <cstdint>

#define BATCH    1024
#define IN_BITS  4096
#define NUM_LUTS 16384
#define KBITS    6
#define NGROUPS  (BATCH / 32)          // 32 groups of 32 batches
#define LTILE    512                   // luts per block (big-smem tile)
#define NTHR     1024                  // 512 LUTs x 2 batch-halves
#define BC       8                     // batch-groups per block

#define PACK_BLOCKS (NGROUPS * (IN_BITS / 256) * 2)   // 1024 (16-row halves)
#define SIGT_BLOCKS (NUM_LUTS / 64)                   // 256 (64-lut patches)
#define CONN_BLOCKS ((NUM_LUTS * KBITS + 255) / 256)  // 384

__device__ uint32_t g_bits[NGROUPS][IN_BITS];        // 512 KB
__device__ uint16_t g_conn[NUM_LUTS * KBITS];        // 196 KB
__device__ float    g_sigT[64 * NUM_LUTS];           // 4 MB, TRANSPOSED [idx][lut]

// ---------------------------------------------------------------------------
// Fused prep: [pack | sigmoid+smem-transpose | conn] dispatched on blockIdx.x.
// ---------------------------------------------------------------------------
__global__ void __launch_bounds__(256) prep_kernel(const float* __restrict__ x,
                                                   const float* __restrict__ table,
                                                   const int* __restrict__ conn32) {
    __shared__ float s[64 * 65];
    const int b = blockIdx.x;
    if (b < PACK_BLOCKS) {
        // pack v2: thread owns (column p, 16-row half) -> MLP 16 coalesced LDGs
        const int g    = b >> 5;
        const int rest = b & 31;
        const int half = rest >> 4;
        const int p    = (rest & 15) * 256 + threadIdx.x;
        const float* xp = x + (size_t)(g * 32 + half * 16) * IN_BITS + p;
        uint32_t a = 0;
#pragma unroll
        for (int j = 0; j < 16; ++j)
            a |= (__ldg(xp + (size_t)j * IN_BITS) > 0.5f ? 1u : 0u) << j;
        ((uint16_t*)g_bits)[2 * ((size_t)g * IN_BITS + p) + half] = (uint16_t)a;
    } else if (b < PACK_BLOCKS + SIGT_BLOCKS) {
        // 64-lut x 64-idx patch: coalesced read -> sigmoid -> smem transpose
        const int lut0 = (b - PACK_BLOCKS) * 64;
        const int t = threadIdx.x;
#pragma unroll
        for (int k = 0; k < 4; ++k) {
            const int i = t + k * 256;
            const int r = i >> 4;
            const int q = i & 15;
            float4 v = *(const float4*)(table + (size_t)(lut0 + r) * 64 + 4 * q);
            v.x = __fdividef(1.0f, 1.0f + __expf(-v.x));
            v.y = __fdividef(1.0f, 1.0f + __expf(-v.y));
            v.z = __fdividef(1.0f, 1.0f + __expf(-v.z));
            v.w = __fdividef(1.0f, 1.0f + __expf(-v.w));
            s[(4 * q + 0) * 65 + r] = v.x;
            s[(4 * q + 1) * 65 + r] = v.y;
            s[(4 * q + 2) * 65 + r] = v.z;
            s[(4 * q + 3) * 65 + r] = v.w;
        }
        __syncthreads();
#pragma unroll
        for (int k = 0; k < 4; ++k) {
            const int i = t + k * 256;
            const int c = i >> 4;
            const int j = (i & 15) * 4;
            float4 o;
            o.x = s[c * 65 + j + 0];
            o.y = s[c * 65 + j + 1];
            o.z = s[c * 65 + j + 2];
            o.w = s[c * 65 + j + 3];
            *(float4*)(g_sigT + (size_t)c * NUM_LUTS + lut0 + j) = o;
        }
    } else {
        // conn dtype sniff: JAX w/o x64 emits int32 despite int64 annotation;
        // true int64 LE would have all odd words == 0 (values < 4096).
        uint32_t acc = 0;
#pragma unroll
        for (int sI = 1; sI < 64; sI += 2) acc |= (uint32_t)conn32[sI];
        const bool is_i64 = (acc == 0u);
        const int i = (b - PACK_BLOCKS - SIGT_BLOCKS) * 256 + threadIdx.x;
        if (i < NUM_LUTS * KBITS) {
            int v = is_i64 ? conn32[2 * i] : conn32[i];
            g_conn[i] = (uint16_t)v;
        }
    }
}

// ---------------------------------------------------------------------------
// cp.async helpers
// ---------------------------------------------------------------------------
__device__ __forceinline__ void cp_async16(void* smem_dst, const void* gsrc) {
    uint32_t s = (uint32_t)__cvta_generic_to_shared(smem_dst);
    asm volatile("cp.async.cg.shared.global [%0], [%1], 16;\n" :: "r"(s), "l"(gsrc));
}
__device__ __forceinline__ void cp_async_commit() {
    asm volatile("cp.async.commit_group;\n" ::: "memory");
}
__device__ __forceinline__ void cp_async_wait0() {
    asm volatile("cp.async.wait_group 0;\n" ::: "memory");
}

// ---------------------------------------------------------------------------
// Main LUT kernel. block = 1024 = 512 LUTs x 2 batch-halves, grid (32,4)
// = 128 CTAs, 1 CTA/SM (single wave) at 50% occupancy.
// smem: 2x16 KB bits (cp.async double-buffered) + 128 KB transposed table
// stab[idx][l] (stride 512 -> LDS bank = lane -> conflict-free) = 160 KB.
// Same per-CTA traffic as round 13 (16 MB bits total) with 2x the warps.
// ---------------------------------------------------------------------------
__global__ void __launch_bounds__(NTHR, 1) lut_kernel(float* __restrict__ out) {
    extern __shared__ uint32_t smem[];
    uint32_t* sb0  = smem;                          // bits buffer 0
    uint32_t* sb1  = smem + IN_BITS;                // bits buffer 1
    float*    stab = (float*)(smem + 2 * IN_BITS);  // [64][LTILE]

    const int t       = threadIdx.x;
    const int l       = t & (LTILE - 1);
    const int h       = t >> 9;                     // batch half
    const int lutbase = blockIdx.x * LTILE;
    const int g0      = blockIdx.y * BC;
    const int lut     = lutbase + l;

    // Prefetch g0's bit column (async): one 16B op per thread.
    {
        const uint4* src = (const uint4*)g_bits[g0];
#pragma unroll
        for (int i = t; i < IN_BITS / 4; i += NTHR)
            cp_async16((uint4*)sb0 + i, src + i);
        cp_async_commit();
    }

    // Transposed table tile: stab[idx][l] <- g_sigT[idx][lutbase+l].
    {
#pragma unroll
        for (int i = t; i < 64 * (LTILE / 4); i += NTHR) {
            const int idx = i >> 7, c = (i & 127) * 4;
            *(float4*)(stab + idx * LTILE + c) =
                *(const float4*)(g_sigT + (size_t)idx * NUM_LUTS + lutbase + c);
        }
    }

    const uint16_t* cp = &g_conn[(size_t)lut * KBITS];
    const int c0 = cp[0], c1 = cp[1], c2 = cp[2], c3 = cp[3], c4 = cp[4], c5 = cp[5];
    const float* scol = stab + l;                   // this LUT's column
    const int jbase = h * 4;

    cp_async_wait0();
    __syncthreads();

#pragma unroll 1
    for (int g = g0; g < g0 + BC; ++g) {
        uint32_t* cur = ((g - g0) & 1) ? sb1 : sb0;
        uint32_t* nxt = ((g - g0) & 1) ? sb0 : sb1;

        if (g + 1 < g0 + BC) {
            const uint4* src = (const uint4*)g_bits[g + 1];
#pragma unroll
            for (int i = t; i < IN_BITS / 4; i += NTHR)
                cp_async16((uint4*)nxt + i, src + i);
            cp_async_commit();
        }

        const uint32_t w0 = cur[c0], w1 = cur[c1], w2 = cur[c2];
        const uint32_t w3 = cur[c3], w4 = cur[c4], w5 = cur[c5];

        float* op = out + (size_t)(g * 32 + jbase) * NUM_LUTS + lut;
#pragma unroll
        for (int jj = 0; jj < 4; ++jj) {
            const int j = jbase + jj;
            // four 6-bit indices at once (bits j, j+8, j+16, j+24 of each word)
            uint32_t acc =   ((w0 >> j) & 0x01010101u);
            acc = acc * 2u + ((w1 >> j) & 0x01010101u);
            acc = acc * 2u + ((w2 >> j) & 0x01010101u);
            acc = acc * 2u + ((w3 >> j) & 0x01010101u);
            acc = acc * 2u + ((w4 >> j) & 0x01010101u);
            acc = acc * 2u + ((w5 >> j) & 0x01010101u);
            const unsigned i0 = acc & 0xFFu;
            const unsigned i1 = __byte_perm(acc, 0, 0x4441);
            const unsigned i2 = __byte_perm(acc, 0, 0x4442);
            const unsigned i3 = acc >> 24;
            float v0 = scol[i0 * LTILE];            // conflict-free LDS
            float v1 = scol[i1 * LTILE];
            float v2 = scol[i2 * LTILE];
            float v3 = scol[i3 * LTILE];
            __stcs(op + (size_t)jj * NUM_LUTS, v0);
            __stcs(op + (size_t)(jj + 8)  * NUM_LUTS, v1);
            __stcs(op + (size_t)(jj + 16) * NUM_LUTS, v2);
            __stcs(op + (size_t)(jj + 24) * NUM_LUTS, v3);
        }

        cp_async_wait0();
        __syncthreads();
    }
}

// ---------------------------------------------------------------------------
extern "C" void kernel_launch(void* const* d_in, const int* in_sizes, int n_in,
                              void* d_out, int out_size) {
    const float* x    = (const float*)d_in[0];   // (1024, 4096) f32
    const float* tab  = (const float*)d_in[1];   // (16384, 64) f32
    const int*   conn = (const int*)d_in[2];     // (16384, 6) i32 (sniffed)
    float*       out  = (float*)d_out;           // (1024, 16384) f32

    static const int SMEM = (2 * IN_BITS + 64 * LTILE) * 4;  // 163840 B
    cudaFuncSetAttribute(lut_kernel, cudaFuncAttributeMaxDynamicSharedMemorySize, SMEM);

    prep_kernel<<<PACK_BLOCKS + SIGT_BLOCKS + CONN_BLOCKS, 256>>>(x, tab, conn);

    dim3 gridC(NUM_LUTS / LTILE, NGROUPS / BC);          // (32, 4)
    lut_kernel<<<gridC, NTHR, SMEM>>>(out);
}

// round 16
// speedup vs baseline: 1.6576x; 1.6576x over previous
#include <cuda_runtime.h>
#include <cuda_fp16.h>
#include <cstdint>

#define BATCH    1024
#define IN_BITS  4096
#define NUM_LUTS 16384
#define KBITS    6
#define NGROUPS  (BATCH / 32)          // 32 groups of 32 batches
#define LTILE    512                   // luts per block
#define NTHR     512                   // thread = one LUT
#define BC       8                     // batch-groups per block

#define PACK_BLOCKS (NGROUPS * (IN_BITS / 256) * 2)   // 1024 (16-row halves)
#define SIGT_BLOCKS (NUM_LUTS / 64)                   // 256 (64-lut patches)
#define CONN_BLOCKS ((NUM_LUTS * KBITS + 255) / 256)  // 384

__device__ uint32_t g_bits[NGROUPS][IN_BITS];        // 512 KB
__device__ uint16_t g_conn[NUM_LUTS * KBITS];        // 196 KB
// Pair-packed sigmoided table, transposed: word j of lut = half2(sig[2j], sig[2j+1])
__device__ uint32_t g_sigTh[32 * NUM_LUTS];          // 2 MB, [pair][lut]

// ---------------------------------------------------------------------------
// Fused prep: [pack | sigmoid+pack+transpose | conn] dispatched on blockIdx.x.
// ---------------------------------------------------------------------------
__global__ void __launch_bounds__(256) prep_kernel(const float* __restrict__ x,
                                                   const float* __restrict__ table,
                                                   const int* __restrict__ conn32) {
    __shared__ uint32_t s2[32 * 65];   // [pair][lut] patch, pad 65
    const int b = blockIdx.x;
    if (b < PACK_BLOCKS) {
        // pack v2: thread owns (column p, 16-row half) -> MLP 16 coalesced LDGs
        const int g    = b >> 5;
        const int rest = b & 31;
        const int half = rest >> 4;
        const int p    = (rest & 15) * 256 + threadIdx.x;
        const float* xp = x + (size_t)(g * 32 + half * 16) * IN_BITS + p;
        uint32_t a = 0;
#pragma unroll
        for (int j = 0; j < 16; ++j)
            a |= (__ldg(xp + (size_t)j * IN_BITS) > 0.5f ? 1u : 0u) << j;
        ((uint16_t*)g_bits)[2 * ((size_t)g * IN_BITS + p) + half] = (uint16_t)a;
    } else if (b < PACK_BLOCKS + SIGT_BLOCKS) {
        // 64-lut patch: read float2 pair -> sigmoid -> half2 pack -> smem
        // transpose -> coalesced uint4 writes to g_sigTh[pair][lut].
        const int lut0 = (b - PACK_BLOCKS) * 64;
        const int t = threadIdx.x;
#pragma unroll
        for (int k = 0; k < 8; ++k) {
            const int i = t + k * 256;      // 0..2047
            const int r = i >> 5;           // lut in patch
            const int j = i & 31;           // pair index
            float2 v = *(const float2*)(table + (size_t)(lut0 + r) * 64 + 2 * j);
            float sx = __fdividef(1.0f, 1.0f + __expf(-v.x));
            float sy = __fdividef(1.0f, 1.0f + __expf(-v.y));
            uint32_t lo = (uint32_t)__half_as_ushort(__float2half_rn(sx));
            uint32_t hi = (uint32_t)__half_as_ushort(__float2half_rn(sy));
            s2[j * 65 + r] = lo | (hi << 16);
        }
        __syncthreads();
#pragma unroll
        for (int k = 0; k < 2; ++k) {
            const int i = t + k * 256;      // 0..511 (uint4 index)
            const int j = i >> 4;           // pair row
            const int c = (i & 15) * 4;     // lut quad
            uint4 o;
            o.x = s2[j * 65 + c + 0];
            o.y = s2[j * 65 + c + 1];
            o.z = s2[j * 65 + c + 2];
            o.w = s2[j * 65 + c + 3];
            *(uint4*)(g_sigTh + (size_t)j * NUM_LUTS + lut0 + c) = o;
        }
    } else {
        // conn dtype sniff: JAX w/o x64 emits int32 despite int64 annotation;
        // true int64 LE would have all odd words == 0 (values < 4096).
        uint32_t acc = 0;
#pragma unroll
        for (int sI = 1; sI < 64; sI += 2) acc |= (uint32_t)conn32[sI];
        const bool is_i64 = (acc == 0u);
        const int i = (b - PACK_BLOCKS - SIGT_BLOCKS) * 256 + threadIdx.x;
        if (i < NUM_LUTS * KBITS) {
            int v = is_i64 ? conn32[2 * i] : conn32[i];
            g_conn[i] = (uint16_t)v;
        }
    }
}

// ---------------------------------------------------------------------------
// cp.async helpers
// ---------------------------------------------------------------------------
__device__ __forceinline__ void cp_async16(void* smem_dst, const void* gsrc) {
    uint32_t s = (uint32_t)__cvta_generic_to_shared(smem_dst);
    asm volatile("cp.async.cg.shared.global [%0], [%1], 16;\n" :: "r"(s), "l"(gsrc));
}
__device__ __forceinline__ void cp_async_commit() {
    asm volatile("cp.async.commit_group;\n" ::: "memory");
}
__device__ __forceinline__ void cp_async_wait0() {
    asm volatile("cp.async.wait_group 0;\n" ::: "memory");
}

// fp16 pair lookup: one conflict-free 32-bit LDS + 16-bit select + cvt.
__device__ __forceinline__ float lut_fetch(const uint32_t* __restrict__ scol,
                                           unsigned idx) {
    uint32_t pw = scol[(idx >> 1) * LTILE];
    uint16_t bits = (uint16_t)(pw >> ((idx & 1u) << 4));
    return __half2float(__ushort_as_half(bits));
}

// ---------------------------------------------------------------------------
// Main LUT kernel. block = 512 (thread = one LUT), grid (32,4) = 128 CTAs,
// 2 CTAs/SM (96 KB smem: 2x16 KB bits + 64 KB pair-packed fp16 table).
// Combines round-7 residency (32 warps/SM, independent CTAs) with round-13
// traffic (16 MB bits total). Table LDS stays conflict-free (bank = lane).
// ---------------------------------------------------------------------------
__global__ void __launch_bounds__(NTHR, 2) lut_kernel(float* __restrict__ out) {
    extern __shared__ uint32_t smem[];
    uint32_t* sb0  = smem;                          // bits buffer 0
    uint32_t* sb1  = smem + IN_BITS;                // bits buffer 1
    uint32_t* stab = smem + 2 * IN_BITS;            // [32][LTILE] half2 pairs

    const int t       = threadIdx.x;
    const int lutbase = blockIdx.x * LTILE;
    const int g0      = blockIdx.y * BC;
    const int lut     = lutbase + t;

    // Prefetch g0's bit column (async).
    {
        const uint4* src = (const uint4*)g_bits[g0];
#pragma unroll
        for (int i = t; i < IN_BITS / 4; i += NTHR)
            cp_async16((uint4*)sb0 + i, src + i);
        cp_async_commit();
    }

    // Pair-packed table tile: stab[j][l] <- g_sigTh[j][lutbase+l].
    {
#pragma unroll
        for (int i = t; i < 32 * (LTILE / 4); i += NTHR) {
            const int j = i >> 7, c = (i & 127) * 4;
            *(uint4*)(stab + j * LTILE + c) =
                *(const uint4*)(g_sigTh + (size_t)j * NUM_LUTS + lutbase + c);
        }
    }

    const uint16_t* cp = &g_conn[(size_t)lut * KBITS];
    const int c0 = cp[0], c1 = cp[1], c2 = cp[2], c3 = cp[3], c4 = cp[4], c5 = cp[5];
    const uint32_t* scol = stab + t;                // this LUT's pair column

    cp_async_wait0();
    __syncthreads();

#pragma unroll 1
    for (int g = g0; g < g0 + BC; ++g) {
        uint32_t* cur = ((g - g0) & 1) ? sb1 : sb0;
        uint32_t* nxt = ((g - g0) & 1) ? sb0 : sb1;

        if (g + 1 < g0 + BC) {
            const uint4* src = (const uint4*)g_bits[g + 1];
#pragma unroll
            for (int i = t; i < IN_BITS / 4; i += NTHR)
                cp_async16((uint4*)nxt + i, src + i);
            cp_async_commit();
        }

        const uint32_t w0 = cur[c0], w1 = cur[c1], w2 = cur[c2];
        const uint32_t w3 = cur[c3], w4 = cur[c4], w5 = cur[c5];

        float* op = out + (size_t)(g * 32) * NUM_LUTS + lut;
#pragma unroll
        for (int jj = 0; jj < 8; ++jj) {
            // four 6-bit indices at once (bits jj, jj+8, jj+16, jj+24)
            uint32_t acc =   ((w0 >> jj) & 0x01010101u);
            acc = acc * 2u + ((w1 >> jj) & 0x01010101u);
            acc = acc * 2u + ((w2 >> jj) & 0x01010101u);
            acc = acc * 2u + ((w3 >> jj) & 0x01010101u);
            acc = acc * 2u + ((w4 >> jj) & 0x01010101u);
            acc = acc * 2u + ((w5 >> jj) & 0x01010101u);
            const unsigned i0 = acc & 0xFFu;
            const unsigned i1 = __byte_perm(acc, 0, 0x4441);
            const unsigned i2 = __byte_perm(acc, 0, 0x4442);
            const unsigned i3 = acc >> 24;
            float v0 = lut_fetch(scol, i0);
            float v1 = lut_fetch(scol, i1);
            float v2 = lut_fetch(scol, i2);
            float v3 = lut_fetch(scol, i3);
            __stcs(op + (size_t)jj * NUM_LUTS, v0);
            __stcs(op + (size_t)(jj + 8)  * NUM_LUTS, v1);
            __stcs(op + (size_t)(jj + 16) * NUM_LUTS, v2);
            __stcs(op + (size_t)(jj + 24) * NUM_LUTS, v3);
        }

        cp_async_wait0();
        __syncthreads();
    }
}

// ---------------------------------------------------------------------------
extern "C" void kernel_launch(void* const* d_in, const int* in_sizes, int n_in,
                              void* d_out, int out_size) {
    const float* x    = (const float*)d_in[0];   // (1024, 4096) f32
    const float* tab  = (const float*)d_in[1];   // (16384, 64) f32
    const int*   conn = (const int*)d_in[2];     // (16384, 6) i32 (sniffed)
    float*       out  = (float*)d_out;           // (1024, 16384) f32

    static const int SMEM = (2 * IN_BITS + 32 * LTILE) * 4;  // 98304 B
    cudaFuncSetAttribute(lut_kernel, cudaFuncAttributeMaxDynamicSharedMemorySize, SMEM);

    prep_kernel<<<PACK_BLOCKS + SIGT_BLOCKS + CONN_BLOCKS, 256>>>(x, tab, conn);

    dim3 gridC(NUM_LUTS / LTILE, NGROUPS / BC);          // (32, 4)
    lut_kernel<<<gridC, NTHR, SMEM>>>(out);
}